// round 8
// baseline (speedup 1.0000x reference)
#include <cuda_runtime.h>
#include <cuda_bf16.h>

typedef unsigned long long u64;
typedef unsigned int u32;

#define E_TOT   10000
#define FREQ    44
#define EB      16
#define NBLK    (E_TOT / EB)               // 625, exact
#define LN_EPS  1e-5f

#define MLP_BLOCKS  (E_TOT / 8)                     // 1250
#define W3T_BLOCKS  ((FREQ * 32 * 256 + 255) / 256) // 1408

#define STRIDE  264                         // row stride (floats) for Ts/RB

// scratch
__device__ float g_h[E_TOT * 32];
__device__ float g_w3t[FREQ * 32 * 256];    // [f][m][p], p = ci*16+co

// ---------------------------------------------------------------------------
__device__ __forceinline__ u64 f2fma(u64 a, u64 b, u64 c) {
    u64 d;
    asm("fma.rn.f32x2 %0, %1, %2, %3;" : "=l"(d) : "l"(a), "l"(b), "l"(c));
    return d;
}
__device__ __forceinline__ u64 dup2(float x) {
    u64 d;
    asm("mov.b64 %0, {%1, %1};" : "=l"(d) : "f"(x));
    return d;
}
__device__ __forceinline__ u32 smem_u32(const void* p) {
    u32 a;
    asm("{ .reg .u64 t; cvta.to.shared.u64 t, %1; cvt.u32.u64 %0, t; }" : "=r"(a) : "l"(p));
    return a;
}
__device__ __forceinline__ void cp16(u32 s, const float* g) {
    asm volatile("cp.async.cg.shared.global [%0], [%1], 16;\n" :: "r"(s), "l"(g));
}
__device__ __forceinline__ void cp_commit() {
    asm volatile("cp.async.commit_group;\n");
}
template <int N>
__device__ __forceinline__ void cp_wait() {
    asm volatile("cp.async.wait_group %0;\n" :: "n"(N));
}

// ---------------------------------------------------------------------------
// prep kernel: MLP (first MLP_BLOCKS blocks) + w3 transpose (rest)
// ---------------------------------------------------------------------------
__device__ __forceinline__ float ln_relu_32(float y, float gamma, float beta) {
    float s = y, q = y * y;
    #pragma unroll
    for (int d = 16; d > 0; d >>= 1) {
        s += __shfl_xor_sync(0xffffffffu, s, d);
        q += __shfl_xor_sync(0xffffffffu, q, d);
    }
    float mean = s * (1.0f / 32.0f);
    float var  = q * (1.0f / 32.0f) - mean * mean;
    float r = rsqrtf(var + LN_EPS);
    float v = (y - mean) * r * gamma + beta;
    return fmaxf(v, 0.0f);
}

__global__ void __launch_bounds__(256) prep_kernel(
    const float* __restrict__ inv,
    const float* __restrict__ w1, const float* __restrict__ b1,
    const float* __restrict__ g1, const float* __restrict__ be1,
    const float* __restrict__ w2, const float* __restrict__ b2,
    const float* __restrict__ g2, const float* __restrict__ be2,
    const float* __restrict__ w3)
{
    if (blockIdx.x >= MLP_BLOCKS) {
        int idx = (blockIdx.x - MLP_BLOCKS) * 256 + threadIdx.x;
        if (idx < FREQ * 32 * 256) {
            int p = idx & 255;
            int m = (idx >> 8) & 31;
            int f = idx >> 13;
            int row = (p & 15) * 704 + (p >> 4) * 44 + f;
            g_w3t[idx] = w3[row * 32 + m];
        }
        return;
    }

    __shared__ float w1_s[32 * 16];
    __shared__ float w2_s[32 * 32];
    __shared__ float p_s[6 * 32];

    int tid = threadIdx.x;
    for (int i = tid; i < 512;  i += 256) w1_s[i] = w1[i];
    for (int i = tid; i < 1024; i += 256) w2_s[i] = w2[i];
    if (tid < 32) {
        p_s[tid]       = b1[tid];
        p_s[32  + tid] = g1[tid];
        p_s[64  + tid] = be1[tid];
        p_s[96  + tid] = b2[tid];
        p_s[128 + tid] = g2[tid];
        p_s[160 + tid] = be2[tid];
    }
    __syncthreads();

    int w = tid >> 5;
    int m = tid & 31;
    int e = blockIdx.x * 8 + w;

    float xv = (m < 16) ? inv[e * 16 + m] : 0.0f;

    float y = p_s[m];
    #pragma unroll
    for (int in = 0; in < 16; in++)
        y = fmaf(__shfl_sync(0xffffffffu, xv, in), w1_s[m * 16 + in], y);
    y = ln_relu_32(y, p_s[32 + m], p_s[64 + m]);

    float y2 = p_s[96 + m];
    #pragma unroll
    for (int k = 0; k < 32; k++)
        y2 = fmaf(__shfl_sync(0xffffffffu, y, k), w2_s[m * 32 + k], y2);
    y2 = ln_relu_32(y2, p_s[128 + m], p_s[160 + m]);

    g_h[e * 32 + m] = y2;
}

// ---------------------------------------------------------------------------
// conv kernel: EB=16 edges, 128 threads/block, 625 blocks (exact cover).
//
// smem (floats):
//   Ts[16][264]  T slice (row stride 264 -> cross-edge reads conflict-free)
//   RB[16][264]  OVERLAY: basis slice (bb) during cp/step2, then R slice (Rs)
//   hs[32][16]   h transposed: hs[m][e]
//
// per f:
//   barA (prev step4 done; overlay free)
//   issue cp.async: basis slice f -> RB (each 16B exactly once); commit
//   step3: accR[8 e-pairs][2 p] from g_w3t (LDG.64) x hs (LDS.128)  [regs]
//   cp_wait + barB
//   step2: T rows from RB + features (global, L1-hot); store Ts
//   barC  (all bb reads done; Ts ready)
//   store accR -> RB (as Rs)
//   barD
//   step4: accO += R * T
// ---------------------------------------------------------------------------
__global__ void __launch_bounds__(128, 6) conv_main_kernel(
    const float* __restrict__ features,  // [E,16,16]
    const float* __restrict__ basis,     // [E,16,44,16]
    float*       __restrict__ out)       // [E,16,16]
{
    extern __shared__ float sm[];
    float* Ts = sm;                // 16*264 = 4224
    float* RB = sm + 4224;         // 16*264 = 4224  (bb / Rs overlay)
    float* hs = sm + 8448;         // 32*16  = 512   -> total 8960 floats

    const int t  = threadIdx.x;
    const int e0 = blockIdx.x * EB;

    // ---- stage hs[m][e] ----
    #pragma unroll
    for (int i = 0; i < 4; i++) {
        int idx = t + i * 128;
        int m = idx >> 4, e = idx & 15;
        hs[m * 16 + e] = g_h[(e0 + e) * 32 + m];
    }

    // ---- roles ----
    const int e2  = t >> 3;        // edge for step2/step4 (0..15)
    const int ci0 = t & 7;         // ci half-index / co for step4
    const int p0  = t * 2;         // step3 p-pair (0..254)

    // cp.async: rows t and t+128 of the 256 (e,in) rows
    const float* cpsrc0 = basis + (size_t)(e0 + (t >> 4)) * 11264 + (t & 15) * 704;
    const float* cpsrc1 = basis + (size_t)(e0 + 8 + (t >> 4)) * 11264 + (t & 15) * 704;
    const u32 rb_base = smem_u32(RB);
    const u32 cpdst0 = rb_base + ((t >> 4) * STRIDE + (t & 15) * 16) * 4;
    const u32 cpdst1 = rb_base + (((t >> 4) + 8) * STRIDE + (t & 15) * 16) * 4;

    // features rows for (e2, ci0) and (e2, ci0+8)
    const float4* fpa = reinterpret_cast<const float4*>(features + ((size_t)(e0 + e2) * 16 + ci0) * 16);
    const float4* fpb = reinterpret_cast<const float4*>(features + ((size_t)(e0 + e2) * 16 + ci0 + 8) * 16);

    u64 accO[2][8];
    #pragma unroll
    for (int r = 0; r < 2; r++)
        #pragma unroll
        for (int i = 0; i < 8; i++) accO[r][i] = 0ull;

    for (int f = 0; f < FREQ; f++) {
        __syncthreads();   // barA: hs ready (f=0) / prev step4 done (f>0)

        // ---- issue cp.async for slice f ----
        {
            const float* g0 = cpsrc0 + f * 16;
            const float* g1 = cpsrc1 + f * 16;
            #pragma unroll
            for (int q = 0; q < 4; q++) cp16(cpdst0 + q * 16, g0 + q * 4);
            #pragma unroll
            for (int q = 0; q < 4; q++) cp16(cpdst1 + q * 16, g1 + q * 4);
            cp_commit();
        }

        // ---- step3: R[16e][p0..p0+1], e packed in f32x2 pairs ----
        u64 accR[8][2];
        #pragma unroll
        for (int i = 0; i < 8; i++) { accR[i][0] = 0ull; accR[i][1] = 0ull; }
        {
            const float* wp = g_w3t + (size_t)f * 8192 + p0;
            #pragma unroll 8
            for (int m = 0; m < 32; m++) {
                float2 wv = *reinterpret_cast<const float2*>(wp + m * 256);
                u64 w0 = dup2(wv.x);
                u64 w1 = dup2(wv.y);
                const float* hb = hs + m * 16;
                ulonglong2 hA = *reinterpret_cast<const ulonglong2*>(hb);
                ulonglong2 hB = *reinterpret_cast<const ulonglong2*>(hb + 4);
                ulonglong2 hC = *reinterpret_cast<const ulonglong2*>(hb + 8);
                ulonglong2 hD = *reinterpret_cast<const ulonglong2*>(hb + 12);
                accR[0][0] = f2fma(hA.x, w0, accR[0][0]); accR[0][1] = f2fma(hA.x, w1, accR[0][1]);
                accR[1][0] = f2fma(hA.y, w0, accR[1][0]); accR[1][1] = f2fma(hA.y, w1, accR[1][1]);
                accR[2][0] = f2fma(hB.x, w0, accR[2][0]); accR[2][1] = f2fma(hB.x, w1, accR[2][1]);
                accR[3][0] = f2fma(hB.y, w0, accR[3][0]); accR[3][1] = f2fma(hB.y, w1, accR[3][1]);
                accR[4][0] = f2fma(hC.x, w0, accR[4][0]); accR[4][1] = f2fma(hC.x, w1, accR[4][1]);
                accR[5][0] = f2fma(hC.y, w0, accR[5][0]); accR[5][1] = f2fma(hC.y, w1, accR[5][1]);
                accR[6][0] = f2fma(hD.x, w0, accR[6][0]); accR[6][1] = f2fma(hD.x, w1, accR[6][1]);
                accR[7][0] = f2fma(hD.y, w0, accR[7][0]); accR[7][1] = f2fma(hD.y, w1, accR[7][1]);
            }
        }

        cp_wait<0>();
        __syncthreads();   // barB: basis slice in RB visible to all

        // ---- step2: T rows (e2, ci0) and (e2, ci0+8) ----
        {
            u64 tA[8], tB[8];
            #pragma unroll
            for (int i = 0; i < 8; i++) { tA[i] = 0ull; tB[i] = 0ull; }

            const float* bp = RB + e2 * STRIDE;
            #pragma unroll 4
            for (int in = 0; in < 16; in++) {
                const float* q = bp + in * 16;
                ulonglong2 x0 = *reinterpret_cast<const ulonglong2*>(q);
                ulonglong2 x1 = *reinterpret_cast<const ulonglong2*>(q + 4);
                ulonglong2 x2 = *reinterpret_cast<const ulonglong2*>(q + 8);
                ulonglong2 x3 = *reinterpret_cast<const ulonglong2*>(q + 12);
                float4 a4 = fpa[in >> 2];
                float4 b4 = fpb[in >> 2];
                float av = (in & 3) == 0 ? a4.x : (in & 3) == 1 ? a4.y : (in & 3) == 2 ? a4.z : a4.w;
                float bv = (in & 3) == 0 ? b4.x : (in & 3) == 1 ? b4.y : (in & 3) == 2 ? b4.z : b4.w;
                u64 da = dup2(av);
                u64 db = dup2(bv);
                tA[0] = f2fma(da, x0.x, tA[0]); tA[1] = f2fma(da, x0.y, tA[1]);
                tA[2] = f2fma(da, x1.x, tA[2]); tA[3] = f2fma(da, x1.y, tA[3]);
                tA[4] = f2fma(da, x2.x, tA[4]); tA[5] = f2fma(da, x2.y, tA[5]);
                tA[6] = f2fma(da, x3.x, tA[6]); tA[7] = f2fma(da, x3.y, tA[7]);
                tB[0] = f2fma(db, x0.x, tB[0]); tB[1] = f2fma(db, x0.y, tB[1]);
                tB[2] = f2fma(db, x1.x, tB[2]); tB[3] = f2fma(db, x1.y, tB[3]);
                tB[4] = f2fma(db, x2.x, tB[4]); tB[5] = f2fma(db, x2.y, tB[5]);
                tB[6] = f2fma(db, x3.x, tB[6]); tB[7] = f2fma(db, x3.y, tB[7]);
            }
            float* ta = Ts + e2 * STRIDE + ci0 * 16;
            float* tb = ta + 128;          // ci0 + 8
            #pragma unroll
            for (int k = 0; k < 4; k++) {
                *reinterpret_cast<ulonglong2*>(ta + (k << 2)) = make_ulonglong2(tA[2*k], tA[2*k+1]);
                *reinterpret_cast<ulonglong2*>(tb + (k << 2)) = make_ulonglong2(tB[2*k], tB[2*k+1]);
            }
        }

        __syncthreads();   // barC: all bb reads done; Ts ready

        // ---- store accR into RB (now Rs) ----
        #pragma unroll
        for (int i = 0; i < 8; i++) {
            float2 a0 = *reinterpret_cast<float2*>(&accR[i][0]);   // (e=2i, e=2i+1) @ p0
            float2 a1 = *reinterpret_cast<float2*>(&accR[i][1]);   // @ p0+1
            *reinterpret_cast<float2*>(RB + (2*i)     * STRIDE + p0) = make_float2(a0.x, a1.x);
            *reinterpret_cast<float2*>(RB + (2*i + 1) * STRIDE + p0) = make_float2(a0.y, a1.y);
        }

        __syncthreads();   // barD: Rs ready

        // ---- step4: accO[co half r] += R[e2][c*16+co] * T[e2][c][o] ----
        {
            const float* Te = Ts + e2 * STRIDE;
            const float* Re = RB + e2 * STRIDE;
            #pragma unroll 4
            for (int c = 0; c < 16; c++) {
                float r0 = Re[c * 16 + ci0];
                float r1 = Re[c * 16 + ci0 + 8];
                u64 d0 = dup2(r0);
                u64 d1 = dup2(r1);
                const float* tc = Te + c * 16;
                ulonglong2 x0 = *reinterpret_cast<const ulonglong2*>(tc);
                ulonglong2 x1 = *reinterpret_cast<const ulonglong2*>(tc + 4);
                ulonglong2 x2 = *reinterpret_cast<const ulonglong2*>(tc + 8);
                ulonglong2 x3 = *reinterpret_cast<const ulonglong2*>(tc + 12);
                accO[0][0] = f2fma(d0, x0.x, accO[0][0]); accO[0][1] = f2fma(d0, x0.y, accO[0][1]);
                accO[0][2] = f2fma(d0, x1.x, accO[0][2]); accO[0][3] = f2fma(d0, x1.y, accO[0][3]);
                accO[0][4] = f2fma(d0, x2.x, accO[0][4]); accO[0][5] = f2fma(d0, x2.y, accO[0][5]);
                accO[0][6] = f2fma(d0, x3.x, accO[0][6]); accO[0][7] = f2fma(d0, x3.y, accO[0][7]);
                accO[1][0] = f2fma(d1, x0.x, accO[1][0]); accO[1][1] = f2fma(d1, x0.y, accO[1][1]);
                accO[1][2] = f2fma(d1, x1.x, accO[1][2]); accO[1][3] = f2fma(d1, x1.y, accO[1][3]);
                accO[1][4] = f2fma(d1, x2.x, accO[1][4]); accO[1][5] = f2fma(d1, x2.y, accO[1][5]);
                accO[1][6] = f2fma(d1, x3.x, accO[1][6]); accO[1][7] = f2fma(d1, x3.y, accO[1][7]);
            }
        }
    }

    // ---- epilogue: out[e2][ci0][0..15] and out[e2][ci0+8][0..15] ----
    {
        float* op0 = out + ((size_t)(e0 + e2) * 16 + ci0) * 16;
        float* op1 = op0 + 128;   // ci0 + 8
        *reinterpret_cast<ulonglong2*>(op0)      = make_ulonglong2(accO[0][0], accO[0][1]);
        *reinterpret_cast<ulonglong2*>(op0 + 4)  = make_ulonglong2(accO[0][2], accO[0][3]);
        *reinterpret_cast<ulonglong2*>(op0 + 8)  = make_ulonglong2(accO[0][4], accO[0][5]);
        *reinterpret_cast<ulonglong2*>(op0 + 12) = make_ulonglong2(accO[0][6], accO[0][7]);
        *reinterpret_cast<ulonglong2*>(op1)      = make_ulonglong2(accO[1][0], accO[1][1]);
        *reinterpret_cast<ulonglong2*>(op1 + 4)  = make_ulonglong2(accO[1][2], accO[1][3]);
        *reinterpret_cast<ulonglong2*>(op1 + 8)  = make_ulonglong2(accO[1][4], accO[1][5]);
        *reinterpret_cast<ulonglong2*>(op1 + 12) = make_ulonglong2(accO[1][6], accO[1][7]);
    }
}

// ---------------------------------------------------------------------------
extern "C" void kernel_launch(void* const* d_in, const int* in_sizes, int n_in,
                              void* d_out, int out_size)
{
    const float* features = (const float*)d_in[0];
    const float* inv      = (const float*)d_in[1];
    const float* basis    = (const float*)d_in[2];
    const float* w1  = (const float*)d_in[3];
    const float* b1  = (const float*)d_in[4];
    const float* g1  = (const float*)d_in[5];
    const float* be1 = (const float*)d_in[6];
    const float* w2  = (const float*)d_in[7];
    const float* b2  = (const float*)d_in[8];
    const float* g2  = (const float*)d_in[9];
    const float* be2 = (const float*)d_in[10];
    const float* w3  = (const float*)d_in[11];
    float* out = (float*)d_out;

    const int smem_bytes = 8960 * 4;   // 35840
    cudaFuncSetAttribute(conv_main_kernel,
                         cudaFuncAttributeMaxDynamicSharedMemorySize, smem_bytes);

    prep_kernel<<<MLP_BLOCKS + W3T_BLOCKS, 256>>>(inv, w1, b1, g1, be1,
                                                  w2, b2, g2, be2, w3);
    conv_main_kernel<<<NBLK, 128, smem_bytes>>>(features, basis, out);
}

// round 10
// speedup vs baseline: 1.2582x; 1.2582x over previous
#include <cuda_runtime.h>
#include <cuda_bf16.h>

typedef unsigned long long u64;
typedef unsigned int u32;

#define E_TOT   10000
#define FREQ    44
#define EB      16
#define NBLK    (E_TOT / EB)               // 625, exact
#define LN_EPS  1e-5f

#define MLP_BLOCKS  (E_TOT / 8)                     // 1250
#define W3T_BLOCKS  ((FREQ * 32 * 256 + 255) / 256) // 1408

#define GE      64                                  // edges per gemm block
#define GEB     ((E_TOT + GE - 1) / GE)             // 157

#define STRIDE  264
#define BUF     (EB * STRIDE)                       // 4224 floats per slice buffer

// scratch
__device__ float g_h[E_TOT * 32];
__device__ float g_w3t[FREQ * 32 * 256];            // [f][m][p], p = ci*16+co
__device__ float g_R[(size_t)E_TOT * FREQ * 256];   // [e][f][p]  (~450 MB)

// ---------------------------------------------------------------------------
__device__ __forceinline__ u64 f2fma(u64 a, u64 b, u64 c) {
    u64 d;
    asm("fma.rn.f32x2 %0, %1, %2, %3;" : "=l"(d) : "l"(a), "l"(b), "l"(c));
    return d;
}
__device__ __forceinline__ u64 dup2(float x) {
    u64 d;
    asm("mov.b64 %0, {%1, %1};" : "=l"(d) : "f"(x));
    return d;
}
__device__ __forceinline__ u32 smem_u32(const void* p) {
    u32 a;
    asm("{ .reg .u64 t; cvta.to.shared.u64 t, %1; cvt.u32.u64 %0, t; }" : "=r"(a) : "l"(p));
    return a;
}
__device__ __forceinline__ void cp16(u32 s, const float* g) {
    asm volatile("cp.async.cg.shared.global [%0], [%1], 16;\n" :: "r"(s), "l"(g));
}
__device__ __forceinline__ void cp_commit() {
    asm volatile("cp.async.commit_group;\n");
}
template <int N>
__device__ __forceinline__ void cp_wait() {
    asm volatile("cp.async.wait_group %0;\n" :: "n"(N));
}

// ---------------------------------------------------------------------------
// prep kernel: MLP (first MLP_BLOCKS blocks) + w3 transpose (rest)
// ---------------------------------------------------------------------------
__device__ __forceinline__ float ln_relu_32(float y, float gamma, float beta) {
    float s = y, q = y * y;
    #pragma unroll
    for (int d = 16; d > 0; d >>= 1) {
        s += __shfl_xor_sync(0xffffffffu, s, d);
        q += __shfl_xor_sync(0xffffffffu, q, d);
    }
    float mean = s * (1.0f / 32.0f);
    float var  = q * (1.0f / 32.0f) - mean * mean;
    float r = rsqrtf(var + LN_EPS);
    float v = (y - mean) * r * gamma + beta;
    return fmaxf(v, 0.0f);
}

__global__ void __launch_bounds__(256) prep_kernel(
    const float* __restrict__ inv,
    const float* __restrict__ w1, const float* __restrict__ b1,
    const float* __restrict__ g1, const float* __restrict__ be1,
    const float* __restrict__ w2, const float* __restrict__ b2,
    const float* __restrict__ g2, const float* __restrict__ be2,
    const float* __restrict__ w3)
{
    if (blockIdx.x >= MLP_BLOCKS) {
        int idx = (blockIdx.x - MLP_BLOCKS) * 256 + threadIdx.x;
        if (idx < FREQ * 32 * 256) {
            int p = idx & 255;
            int m = (idx >> 8) & 31;
            int f = idx >> 13;
            int row = (p & 15) * 704 + (p >> 4) * 44 + f;
            g_w3t[idx] = w3[row * 32 + m];
        }
        return;
    }

    __shared__ float w1_s[32 * 16];
    __shared__ float w2_s[32 * 32];
    __shared__ float p_s[6 * 32];

    int tid = threadIdx.x;
    for (int i = tid; i < 512;  i += 256) w1_s[i] = w1[i];
    for (int i = tid; i < 1024; i += 256) w2_s[i] = w2[i];
    if (tid < 32) {
        p_s[tid]       = b1[tid];
        p_s[32  + tid] = g1[tid];
        p_s[64  + tid] = be1[tid];
        p_s[96  + tid] = b2[tid];
        p_s[128 + tid] = g2[tid];
        p_s[160 + tid] = be2[tid];
    }
    __syncthreads();

    int w = tid >> 5;
    int m = tid & 31;
    int e = blockIdx.x * 8 + w;

    float xv = (m < 16) ? inv[e * 16 + m] : 0.0f;

    float y = p_s[m];
    #pragma unroll
    for (int in = 0; in < 16; in++)
        y = fmaf(__shfl_sync(0xffffffffu, xv, in), w1_s[m * 16 + in], y);
    y = ln_relu_32(y, p_s[32 + m], p_s[64 + m]);

    float y2 = p_s[96 + m];
    #pragma unroll
    for (int k = 0; k < 32; k++)
        y2 = fmaf(__shfl_sync(0xffffffffu, y, k), w2_s[m * 32 + k], y2);
    y2 = ln_relu_32(y2, p_s[128 + m], p_s[160 + m]);

    g_h[e * 32 + m] = y2;
}

// ---------------------------------------------------------------------------
// rw GEMM kernel: g_R[e][f][p] = sum_m g_h[e][m] * g_w3t[f][m][p]
// block = (ebi, f): 64 edges x 256 p. 256 threads: thread = (e-group of 16, p-quad).
// ---------------------------------------------------------------------------
__global__ void __launch_bounds__(256) rw_gemm_kernel()
{
    __shared__ float hs2[32 * 64];    // [m][e]

    const int t   = threadIdx.x;
    const int f   = blockIdx.x % FREQ;
    const int eb0 = (blockIdx.x / FREQ) * GE;

    #pragma unroll
    for (int i = 0; i < 8; i++) {
        int idx = t + i * 256;
        int e = idx >> 5, m = idx & 31;
        hs2[m * 64 + e] = (eb0 + e < E_TOT) ? g_h[(eb0 + e) * 32 + m] : 0.0f;
    }
    __syncthreads();

    const int p0 = (t & 63) * 4;      // p quad
    const int eg = t >> 6;            // e-group (16 edges)

    const float* wp = g_w3t + (size_t)f * 8192 + p0;
    const float* hp = hs2 + eg * 16;

    u64 acc[8][4];
    #pragma unroll
    for (int i = 0; i < 8; i++)
        #pragma unroll
        for (int j = 0; j < 4; j++) acc[i][j] = 0ull;

    #pragma unroll 8
    for (int m = 0; m < 32; m++) {
        float4 wv = *reinterpret_cast<const float4*>(wp + m * 256);
        u64 w0 = dup2(wv.x), w1 = dup2(wv.y), w2v = dup2(wv.z), w3v = dup2(wv.w);
        const u64* hq = reinterpret_cast<const u64*>(hp + m * 64);
        #pragma unroll
        for (int i = 0; i < 8; i++) {
            u64 hv = hq[i];
            acc[i][0] = f2fma(hv, w0,  acc[i][0]);
            acc[i][1] = f2fma(hv, w1,  acc[i][1]);
            acc[i][2] = f2fma(hv, w2v, acc[i][2]);
            acc[i][3] = f2fma(hv, w3v, acc[i][3]);
        }
    }

    #pragma unroll
    for (int i = 0; i < 8; i++) {
        float2 a0 = *reinterpret_cast<float2*>(&acc[i][0]);
        float2 a1 = *reinterpret_cast<float2*>(&acc[i][1]);
        float2 a2 = *reinterpret_cast<float2*>(&acc[i][2]);
        float2 a3 = *reinterpret_cast<float2*>(&acc[i][3]);
        int ee = eb0 + eg * 16 + 2 * i;
        if (ee < E_TOT)
            *reinterpret_cast<float4*>(g_R + (size_t)ee * 11264 + f * 256 + p0) =
                make_float4(a0.x, a1.x, a2.x, a3.x);
        if (ee + 1 < E_TOT)
            *reinterpret_cast<float4*>(g_R + (size_t)(ee + 1) * 11264 + f * 256 + p0) =
                make_float4(a0.y, a1.y, a2.y, a3.y);
    }
}

// ---------------------------------------------------------------------------
// conv kernel v2: EB=16 edges, 128 threads. Streams basis + R slices via
// cp.async (double-buffered). Prefetch for f+1 is issued AFTER the barrier
// that retires all reads of the target buffer (fixes round-9 WAR race).
// ---------------------------------------------------------------------------
__global__ void __launch_bounds__(128) conv_main_kernel(
    const float* __restrict__ features,  // [E,16,16]
    const float* __restrict__ basis,     // [E,16,44,16]
    float*       __restrict__ out)       // [E,16,16]
{
    extern __shared__ float sm[];
    float* bb = sm;                      // 2*4224
    float* rr = sm + 2 * BUF;            // 2*4224
    float* Ts = sm + 4 * BUF;            // 4224   -> 21120 floats

    const int t  = threadIdx.x;
    const int e0 = blockIdx.x * EB;
    const int e2  = t >> 3;              // edge (0..15)
    const int ci0 = t & 7;               // ci/co half index

    // cp.async roles: chunks idx = t and t+128; idx = e*16 + k
    const int cpe  = t >> 4;             // 0..7
    const int cpk  = t & 15;
    const float* bsrc0 = basis + (size_t)(e0 + cpe)     * 11264 + cpk * 704;  // + f*16
    const float* bsrc1 = basis + (size_t)(e0 + cpe + 8) * 11264 + cpk * 704;
    const float* rsrc0 = g_R   + (size_t)(e0 + cpe)     * 11264 + cpk * 16;   // + f*256
    const float* rsrc1 = g_R   + (size_t)(e0 + cpe + 8) * 11264 + cpk * 16;
    const u32 bb0 = smem_u32(bb) + ((cpe)     * STRIDE + cpk * 16) * 4;
    const u32 bb1 = smem_u32(bb) + ((cpe + 8) * STRIDE + cpk * 16) * 4;
    const u32 rr0 = smem_u32(rr) + ((cpe)     * STRIDE + cpk * 16) * 4;
    const u32 rr1 = smem_u32(rr) + ((cpe + 8) * STRIDE + cpk * 16) * 4;

    // features rows (e2, ci0) and (e2, ci0+8) in registers
    float fA[16], fB[16];
    {
        const float4* pa = reinterpret_cast<const float4*>(features + ((size_t)(e0 + e2) * 16 + ci0) * 16);
        const float4* pb = reinterpret_cast<const float4*>(features + ((size_t)(e0 + e2) * 16 + ci0 + 8) * 16);
        #pragma unroll
        for (int k = 0; k < 4; k++) {
            float4 a = pa[k], b = pb[k];
            fA[4*k] = a.x; fA[4*k+1] = a.y; fA[4*k+2] = a.z; fA[4*k+3] = a.w;
            fB[4*k] = b.x; fB[4*k+1] = b.y; fB[4*k+2] = b.z; fB[4*k+3] = b.w;
        }
    }

    u64 accO[2][8];
    #pragma unroll
    for (int r = 0; r < 2; r++)
        #pragma unroll
        for (int i = 0; i < 8; i++) accO[r][i] = 0ull;

    // prefetch slice f=0 into buffer 0
    {
        #pragma unroll
        for (int q = 0; q < 4; q++) cp16(bb0 + q * 16, bsrc0 + q * 4);
        #pragma unroll
        for (int q = 0; q < 4; q++) cp16(bb1 + q * 16, bsrc1 + q * 4);
        #pragma unroll
        for (int q = 0; q < 4; q++) cp16(rr0 + q * 16, rsrc0 + q * 4);
        #pragma unroll
        for (int q = 0; q < 4; q++) cp16(rr1 + q * 16, rsrc1 + q * 4);
        cp_commit();
    }

    for (int f = 0; f < FREQ; f++) {
        // only group f is in flight here -> wait for it
        cp_wait<0>();
        __syncthreads();   // slice f visible to all; all reads of buffer
                           // (f+1)&1 (from iteration f-1) retired

        // issue prefetch for f+1 (safe: target buffer has no pending readers)
        if (f + 1 < FREQ) {
            const u32 off = ((f + 1) & 1) * (BUF * 4);
            const float* gb0 = bsrc0 + (f + 1) * 16;
            const float* gb1 = bsrc1 + (f + 1) * 16;
            const float* gr0 = rsrc0 + (f + 1) * 256;
            const float* gr1 = rsrc1 + (f + 1) * 256;
            #pragma unroll
            for (int q = 0; q < 4; q++) cp16(bb0 + off + q * 16, gb0 + q * 4);
            #pragma unroll
            for (int q = 0; q < 4; q++) cp16(bb1 + off + q * 16, gb1 + q * 4);
            #pragma unroll
            for (int q = 0; q < 4; q++) cp16(rr0 + off + q * 16, gr0 + q * 4);
            #pragma unroll
            for (int q = 0; q < 4; q++) cp16(rr1 + off + q * 16, gr1 + q * 4);
            cp_commit();
        }

        // ---- step2: T rows (e2, ci0) and (e2, ci0+8) ----
        {
            u64 tA[8], tB[8];
            #pragma unroll
            for (int i = 0; i < 8; i++) { tA[i] = 0ull; tB[i] = 0ull; }

            const float* bp = bb + (f & 1) * BUF + e2 * STRIDE;
            #pragma unroll 4
            for (int in = 0; in < 16; in++) {
                const float* q = bp + in * 16;
                ulonglong2 x0 = *reinterpret_cast<const ulonglong2*>(q);
                ulonglong2 x1 = *reinterpret_cast<const ulonglong2*>(q + 4);
                ulonglong2 x2 = *reinterpret_cast<const ulonglong2*>(q + 8);
                ulonglong2 x3 = *reinterpret_cast<const ulonglong2*>(q + 12);
                u64 da = dup2(fA[in]);
                u64 db = dup2(fB[in]);
                tA[0] = f2fma(da, x0.x, tA[0]); tA[1] = f2fma(da, x0.y, tA[1]);
                tA[2] = f2fma(da, x1.x, tA[2]); tA[3] = f2fma(da, x1.y, tA[3]);
                tA[4] = f2fma(da, x2.x, tA[4]); tA[5] = f2fma(da, x2.y, tA[5]);
                tA[6] = f2fma(da, x3.x, tA[6]); tA[7] = f2fma(da, x3.y, tA[7]);
                tB[0] = f2fma(db, x0.x, tB[0]); tB[1] = f2fma(db, x0.y, tB[1]);
                tB[2] = f2fma(db, x1.x, tB[2]); tB[3] = f2fma(db, x1.y, tB[3]);
                tB[4] = f2fma(db, x2.x, tB[4]); tB[5] = f2fma(db, x2.y, tB[5]);
                tB[6] = f2fma(db, x3.x, tB[6]); tB[7] = f2fma(db, x3.y, tB[7]);
            }
            // Ts store with chunk swizzle kk = k ^ (c&3)
            float* ta = Ts + e2 * STRIDE + ci0 * 16;
            float* tb = ta + 128;
            const int swA = ci0 & 3;
            #pragma unroll
            for (int k = 0; k < 4; k++) {
                int kk = k ^ swA;
                *reinterpret_cast<ulonglong2*>(ta + (kk << 2)) = make_ulonglong2(tA[2*k], tA[2*k+1]);
                *reinterpret_cast<ulonglong2*>(tb + (kk << 2)) = make_ulonglong2(tB[2*k], tB[2*k+1]);
            }
        }

        __syncthreads();   // Ts ready

        // ---- step4: accO[r] += R[e2][c*16 + co_r] * T[e2][c][o] ----
        {
            const float* Te = Ts + e2 * STRIDE;
            const float* Re = rr + (f & 1) * BUF + e2 * STRIDE;
            #pragma unroll 4
            for (int c = 0; c < 16; c++) {
                float r0 = Re[c * 16 + ci0];
                float r1 = Re[c * 16 + ci0 + 8];
                u64 d0 = dup2(r0);
                u64 d1 = dup2(r1);
                const float* tc = Te + c * 16;
                const int sw = c & 3;
                ulonglong2 x0 = *reinterpret_cast<const ulonglong2*>(tc + ((0 ^ sw) << 2));
                ulonglong2 x1 = *reinterpret_cast<const ulonglong2*>(tc + ((1 ^ sw) << 2));
                ulonglong2 x2 = *reinterpret_cast<const ulonglong2*>(tc + ((2 ^ sw) << 2));
                ulonglong2 x3 = *reinterpret_cast<const ulonglong2*>(tc + ((3 ^ sw) << 2));
                accO[0][0] = f2fma(d0, x0.x, accO[0][0]); accO[0][1] = f2fma(d0, x0.y, accO[0][1]);
                accO[0][2] = f2fma(d0, x1.x, accO[0][2]); accO[0][3] = f2fma(d0, x1.y, accO[0][3]);
                accO[0][4] = f2fma(d0, x2.x, accO[0][4]); accO[0][5] = f2fma(d0, x2.y, accO[0][5]);
                accO[0][6] = f2fma(d0, x3.x, accO[0][6]); accO[0][7] = f2fma(d0, x3.y, accO[0][7]);
                accO[1][0] = f2fma(d1, x0.x, accO[1][0]); accO[1][1] = f2fma(d1, x0.y, accO[1][1]);
                accO[1][2] = f2fma(d1, x1.x, accO[1][2]); accO[1][3] = f2fma(d1, x1.y, accO[1][3]);
                accO[1][4] = f2fma(d1, x2.x, accO[1][4]); accO[1][5] = f2fma(d1, x2.y, accO[1][5]);
                accO[1][6] = f2fma(d1, x3.x, accO[1][6]); accO[1][7] = f2fma(d1, x3.y, accO[1][7]);
            }
        }
    }

    // ---- epilogue ----
    {
        float* op0 = out + ((size_t)(e0 + e2) * 16 + ci0) * 16;
        float* op1 = op0 + 128;
        *reinterpret_cast<ulonglong2*>(op0)      = make_ulonglong2(accO[0][0], accO[0][1]);
        *reinterpret_cast<ulonglong2*>(op0 + 4)  = make_ulonglong2(accO[0][2], accO[0][3]);
        *reinterpret_cast<ulonglong2*>(op0 + 8)  = make_ulonglong2(accO[0][4], accO[0][5]);
        *reinterpret_cast<ulonglong2*>(op0 + 12) = make_ulonglong2(accO[0][6], accO[0][7]);
        *reinterpret_cast<ulonglong2*>(op1)      = make_ulonglong2(accO[1][0], accO[1][1]);
        *reinterpret_cast<ulonglong2*>(op1 + 4)  = make_ulonglong2(accO[1][2], accO[1][3]);
        *reinterpret_cast<ulonglong2*>(op1 + 8)  = make_ulonglong2(accO[1][4], accO[1][5]);
        *reinterpret_cast<ulonglong2*>(op1 + 12) = make_ulonglong2(accO[1][6], accO[1][7]);
    }
}

// ---------------------------------------------------------------------------
extern "C" void kernel_launch(void* const* d_in, const int* in_sizes, int n_in,
                              void* d_out, int out_size)
{
    const float* features = (const float*)d_in[0];
    const float* inv      = (const float*)d_in[1];
    const float* basis    = (const float*)d_in[2];
    const float* w1  = (const float*)d_in[3];
    const float* b1  = (const float*)d_in[4];
    const float* g1  = (const float*)d_in[5];
    const float* be1 = (const float*)d_in[6];
    const float* w2  = (const float*)d_in[7];
    const float* b2  = (const float*)d_in[8];
    const float* g2  = (const float*)d_in[9];
    const float* be2 = (const float*)d_in[10];
    const float* w3  = (const float*)d_in[11];
    float* out = (float*)d_out;

    const int smem_bytes = (5 * BUF) * 4;   // 84480
    cudaFuncSetAttribute(conv_main_kernel,
                         cudaFuncAttributeMaxDynamicSharedMemorySize, smem_bytes);

    prep_kernel<<<MLP_BLOCKS + W3T_BLOCKS, 256>>>(inv, w1, b1, g1, be1,
                                                  w2, b2, g2, be2, w3);
    rw_gemm_kernel<<<GEB * FREQ, 256>>>();
    conv_main_kernel<<<NBLK, 128, smem_bytes>>>(features, basis, out);
}

// round 11
// speedup vs baseline: 1.5820x; 1.2573x over previous
#include <cuda_runtime.h>
#include <cuda_bf16.h>

typedef unsigned long long u64;
typedef unsigned int u32;

#define E_TOT   10000
#define FREQ    44
#define EB      8
#define NBLK    (E_TOT / EB)               // 1250, exact
#define LN_EPS  1e-5f

#define MLP_BLOCKS  (E_TOT / 8)                     // 1250
#define W3T_BLOCKS  ((FREQ * 32 * 256 + 255) / 256) // 1408

#define GE      64                                  // edges per gemm block
#define GEB     ((E_TOT + GE - 1) / GE)             // 157

#define STRIDE  272                        // floats per edge-row (bank offset 16)
#define BUF     (EB * STRIDE)              // 2176 floats per slice buffer

// scratch
__device__ float g_h[E_TOT * 32];
__device__ float g_w3t[FREQ * 32 * 256];            // [f][m][p], p = ci*16+co
__device__ float g_R[(size_t)E_TOT * FREQ * 256];   // [e][f][p]  (~450 MB)

// ---------------------------------------------------------------------------
__device__ __forceinline__ u64 f2fma(u64 a, u64 b, u64 c) {
    u64 d;
    asm("fma.rn.f32x2 %0, %1, %2, %3;" : "=l"(d) : "l"(a), "l"(b), "l"(c));
    return d;
}
__device__ __forceinline__ u64 dup2(float x) {
    u64 d;
    asm("mov.b64 %0, {%1, %1};" : "=l"(d) : "f"(x));
    return d;
}
__device__ __forceinline__ u32 smem_u32(const void* p) {
    u32 a;
    asm("{ .reg .u64 t; cvta.to.shared.u64 t, %1; cvt.u32.u64 %0, t; }" : "=r"(a) : "l"(p));
    return a;
}
__device__ __forceinline__ void cp16(u32 s, const float* g) {
    asm volatile("cp.async.cg.shared.global [%0], [%1], 16;\n" :: "r"(s), "l"(g));
}
__device__ __forceinline__ void cp_commit() {
    asm volatile("cp.async.commit_group;\n");
}
template <int N>
__device__ __forceinline__ void cp_wait() {
    asm volatile("cp.async.wait_group %0;\n" :: "n"(N));
}

// ---------------------------------------------------------------------------
// prep kernel: MLP (first MLP_BLOCKS blocks) + w3 transpose (rest)
// ---------------------------------------------------------------------------
__device__ __forceinline__ float ln_relu_32(float y, float gamma, float beta) {
    float s = y, q = y * y;
    #pragma unroll
    for (int d = 16; d > 0; d >>= 1) {
        s += __shfl_xor_sync(0xffffffffu, s, d);
        q += __shfl_xor_sync(0xffffffffu, q, d);
    }
    float mean = s * (1.0f / 32.0f);
    float var  = q * (1.0f / 32.0f) - mean * mean;
    float r = rsqrtf(var + LN_EPS);
    float v = (y - mean) * r * gamma + beta;
    return fmaxf(v, 0.0f);
}

__global__ void __launch_bounds__(256) prep_kernel(
    const float* __restrict__ inv,
    const float* __restrict__ w1, const float* __restrict__ b1,
    const float* __restrict__ g1, const float* __restrict__ be1,
    const float* __restrict__ w2, const float* __restrict__ b2,
    const float* __restrict__ g2, const float* __restrict__ be2,
    const float* __restrict__ w3)
{
    if (blockIdx.x >= MLP_BLOCKS) {
        int idx = (blockIdx.x - MLP_BLOCKS) * 256 + threadIdx.x;
        if (idx < FREQ * 32 * 256) {
            int p = idx & 255;
            int m = (idx >> 8) & 31;
            int f = idx >> 13;
            int row = (p & 15) * 704 + (p >> 4) * 44 + f;
            g_w3t[idx] = w3[row * 32 + m];
        }
        return;
    }

    __shared__ float w1_s[32 * 16];
    __shared__ float w2_s[32 * 32];
    __shared__ float p_s[6 * 32];

    int tid = threadIdx.x;
    for (int i = tid; i < 512;  i += 256) w1_s[i] = w1[i];
    for (int i = tid; i < 1024; i += 256) w2_s[i] = w2[i];
    if (tid < 32) {
        p_s[tid]       = b1[tid];
        p_s[32  + tid] = g1[tid];
        p_s[64  + tid] = be1[tid];
        p_s[96  + tid] = b2[tid];
        p_s[128 + tid] = g2[tid];
        p_s[160 + tid] = be2[tid];
    }
    __syncthreads();

    int w = tid >> 5;
    int m = tid & 31;
    int e = blockIdx.x * 8 + w;

    float xv = (m < 16) ? inv[e * 16 + m] : 0.0f;

    float y = p_s[m];
    #pragma unroll
    for (int in = 0; in < 16; in++)
        y = fmaf(__shfl_sync(0xffffffffu, xv, in), w1_s[m * 16 + in], y);
    y = ln_relu_32(y, p_s[32 + m], p_s[64 + m]);

    float y2 = p_s[96 + m];
    #pragma unroll
    for (int k = 0; k < 32; k++)
        y2 = fmaf(__shfl_sync(0xffffffffu, y, k), w2_s[m * 32 + k], y2);
    y2 = ln_relu_32(y2, p_s[128 + m], p_s[160 + m]);

    g_h[e * 32 + m] = y2;
}

// ---------------------------------------------------------------------------
// rw GEMM kernel: g_R[e][f][p] = sum_m g_h[e][m] * g_w3t[f][m][p]
// ---------------------------------------------------------------------------
__global__ void __launch_bounds__(256) rw_gemm_kernel()
{
    __shared__ float hs2[32 * 64];    // [m][e]

    const int t   = threadIdx.x;
    const int f   = blockIdx.x % FREQ;
    const int eb0 = (blockIdx.x / FREQ) * GE;

    #pragma unroll
    for (int i = 0; i < 8; i++) {
        int idx = t + i * 256;
        int e = idx >> 5, m = idx & 31;
        hs2[m * 64 + e] = (eb0 + e < E_TOT) ? g_h[(eb0 + e) * 32 + m] : 0.0f;
    }
    __syncthreads();

    const int p0 = (t & 63) * 4;
    const int eg = t >> 6;

    const float* wp = g_w3t + (size_t)f * 8192 + p0;
    const float* hp = hs2 + eg * 16;

    u64 acc[8][4];
    #pragma unroll
    for (int i = 0; i < 8; i++)
        #pragma unroll
        for (int j = 0; j < 4; j++) acc[i][j] = 0ull;

    #pragma unroll 8
    for (int m = 0; m < 32; m++) {
        float4 wv = *reinterpret_cast<const float4*>(wp + m * 256);
        u64 w0 = dup2(wv.x), w1 = dup2(wv.y), w2v = dup2(wv.z), w3v = dup2(wv.w);
        const u64* hq = reinterpret_cast<const u64*>(hp + m * 64);
        #pragma unroll
        for (int i = 0; i < 8; i++) {
            u64 hv = hq[i];
            acc[i][0] = f2fma(hv, w0,  acc[i][0]);
            acc[i][1] = f2fma(hv, w1,  acc[i][1]);
            acc[i][2] = f2fma(hv, w2v, acc[i][2]);
            acc[i][3] = f2fma(hv, w3v, acc[i][3]);
        }
    }

    #pragma unroll
    for (int i = 0; i < 8; i++) {
        float2 a0 = *reinterpret_cast<float2*>(&acc[i][0]);
        float2 a1 = *reinterpret_cast<float2*>(&acc[i][1]);
        float2 a2 = *reinterpret_cast<float2*>(&acc[i][2]);
        float2 a3 = *reinterpret_cast<float2*>(&acc[i][3]);
        int ee = eb0 + eg * 16 + 2 * i;
        if (ee < E_TOT)
            *reinterpret_cast<float4*>(g_R + (size_t)ee * 11264 + f * 256 + p0) =
                make_float4(a0.x, a1.x, a2.x, a3.x);
        if (ee + 1 < E_TOT)
            *reinterpret_cast<float4*>(g_R + (size_t)(ee + 1) * 11264 + f * 256 + p0) =
                make_float4(a0.y, a1.y, a2.y, a3.y);
    }
}

// ---------------------------------------------------------------------------
// conv kernel v3: EB=8 edges, 128 threads, thread = (e2, co).
// 43.5 KB smem -> 5 blocks/SM (20 warps) for latency hiding.
// ---------------------------------------------------------------------------
__global__ void __launch_bounds__(128, 5) conv_main_kernel(
    const float* __restrict__ features,  // [E,16,16]
    const float* __restrict__ basis,     // [E,16,44,16]
    float*       __restrict__ out)       // [E,16,16]
{
    extern __shared__ float sm[];
    float* bb = sm;                      // 2*2176
    float* rr = sm + 2 * BUF;            // 2*2176
    float* Ts = sm + 4 * BUF;            // 2176   -> 10880 floats (43520 B)

    const int t  = threadIdx.x;
    const int e0 = blockIdx.x * EB;
    const int e2 = t >> 4;               // edge (0..7)
    const int co = t & 15;               // ci for step2, co for step4

    // ---- cp.async roles: 4 bb chunks + 4 rr chunks, chunk q = t + 128*j ----
    const float* bsrc[4];
    const float* rsrc[4];
    u32 bdst[4], rdst[4];
    const u32 bb_u = smem_u32(bb);
    const u32 rr_u = smem_u32(rr);
    #pragma unroll
    for (int j = 0; j < 4; j++) {
        int q  = t + 128 * j;
        int qe = q >> 6;                 // edge 0..7
        int qo = (q & 63) * 4;           // float offset in 256-float row
        int qi = qo >> 4;                // in index (bb)
        int qz = qo & 15;
        bsrc[j] = basis + (size_t)(e0 + qe) * 11264 + qi * 704 + qz;   // + f*16
        rsrc[j] = g_R   + (size_t)(e0 + qe) * 11264 + qo;              // + f*256
        bdst[j] = bb_u + (qe * STRIDE + qi * 16 + qz) * 4;
        rdst[j] = rr_u + (qe * STRIDE + qo) * 4;
    }

    // ---- features row (e2, co) in registers ----
    float fF[16];
    {
        const float4* fp = reinterpret_cast<const float4*>(features + ((size_t)(e0 + e2) * 16 + co) * 16);
        #pragma unroll
        for (int k = 0; k < 4; k++) {
            float4 v = fp[k];
            fF[4*k] = v.x; fF[4*k+1] = v.y; fF[4*k+2] = v.z; fF[4*k+3] = v.w;
        }
    }

    u64 accO[8];
    #pragma unroll
    for (int i = 0; i < 8; i++) accO[i] = 0ull;

    // prefetch slice f=0 into buffer 0
    #pragma unroll
    for (int j = 0; j < 4; j++) cp16(bdst[j], bsrc[j]);
    #pragma unroll
    for (int j = 0; j < 4; j++) cp16(rdst[j], rsrc[j]);
    cp_commit();

    for (int f = 0; f < FREQ; f++) {
        cp_wait<0>();
        __syncthreads();   // slice f visible; all reads of buffer (f+1)&1 retired

        // issue prefetch for f+1 (target buffer has no pending readers)
        if (f + 1 < FREQ) {
            const u32 off = ((f + 1) & 1) * (BUF * 4);
            #pragma unroll
            for (int j = 0; j < 4; j++) cp16(bdst[j] + off, bsrc[j] + (f + 1) * 16);
            #pragma unroll
            for (int j = 0; j < 4; j++) cp16(rdst[j] + off, rsrc[j] + (f + 1) * 256);
            cp_commit();
        }

        // ---- step2: T[e2][co][0..15] ----
        {
            u64 tacc[8];
            #pragma unroll
            for (int i = 0; i < 8; i++) tacc[i] = 0ull;

            const float* bp = bb + (f & 1) * BUF + e2 * STRIDE;
            #pragma unroll 4
            for (int in = 0; in < 16; in++) {
                const float* q = bp + in * 16;
                ulonglong2 x0 = *reinterpret_cast<const ulonglong2*>(q);
                ulonglong2 x1 = *reinterpret_cast<const ulonglong2*>(q + 4);
                ulonglong2 x2 = *reinterpret_cast<const ulonglong2*>(q + 8);
                ulonglong2 x3 = *reinterpret_cast<const ulonglong2*>(q + 12);
                u64 fd = dup2(fF[in]);
                tacc[0] = f2fma(fd, x0.x, tacc[0]); tacc[1] = f2fma(fd, x0.y, tacc[1]);
                tacc[2] = f2fma(fd, x1.x, tacc[2]); tacc[3] = f2fma(fd, x1.y, tacc[3]);
                tacc[4] = f2fma(fd, x2.x, tacc[4]); tacc[5] = f2fma(fd, x2.y, tacc[5]);
                tacc[6] = f2fma(fd, x3.x, tacc[6]); tacc[7] = f2fma(fd, x3.y, tacc[7]);
            }
            // Ts store with chunk swizzle kk = k ^ (co & 3)
            float* ta = Ts + e2 * STRIDE + co * 16;
            const int sw = co & 3;
            #pragma unroll
            for (int k = 0; k < 4; k++) {
                int kk = k ^ sw;
                *reinterpret_cast<ulonglong2*>(ta + (kk << 2)) =
                    make_ulonglong2(tacc[2*k], tacc[2*k+1]);
            }
        }

        __syncthreads();   // Ts ready

        // ---- step4: accO[o] += R[e2][cc*16+co] * T[e2][cc][o] ----
        {
            const float* Te = Ts + e2 * STRIDE;
            const float* Re = rr + (f & 1) * BUF + e2 * STRIDE;
            #pragma unroll 4
            for (int cc = 0; cc < 16; cc++) {
                float rv = Re[cc * 16 + co];
                u64 rd = dup2(rv);
                const float* tc = Te + cc * 16;
                const int sw = cc & 3;
                ulonglong2 x0 = *reinterpret_cast<const ulonglong2*>(tc + ((0 ^ sw) << 2));
                ulonglong2 x1 = *reinterpret_cast<const ulonglong2*>(tc + ((1 ^ sw) << 2));
                ulonglong2 x2 = *reinterpret_cast<const ulonglong2*>(tc + ((2 ^ sw) << 2));
                ulonglong2 x3 = *reinterpret_cast<const ulonglong2*>(tc + ((3 ^ sw) << 2));
                accO[0] = f2fma(rd, x0.x, accO[0]); accO[1] = f2fma(rd, x0.y, accO[1]);
                accO[2] = f2fma(rd, x1.x, accO[2]); accO[3] = f2fma(rd, x1.y, accO[3]);
                accO[4] = f2fma(rd, x2.x, accO[4]); accO[5] = f2fma(rd, x2.y, accO[5]);
                accO[6] = f2fma(rd, x3.x, accO[6]); accO[7] = f2fma(rd, x3.y, accO[7]);
            }
        }
    }

    // ---- epilogue: out[e2][co][0..15] ----
    {
        float* op = out + ((size_t)(e0 + e2) * 16 + co) * 16;
        *reinterpret_cast<ulonglong2*>(op)      = make_ulonglong2(accO[0], accO[1]);
        *reinterpret_cast<ulonglong2*>(op + 4)  = make_ulonglong2(accO[2], accO[3]);
        *reinterpret_cast<ulonglong2*>(op + 8)  = make_ulonglong2(accO[4], accO[5]);
        *reinterpret_cast<ulonglong2*>(op + 12) = make_ulonglong2(accO[6], accO[7]);
    }
}

// ---------------------------------------------------------------------------
extern "C" void kernel_launch(void* const* d_in, const int* in_sizes, int n_in,
                              void* d_out, int out_size)
{
    const float* features = (const float*)d_in[0];
    const float* inv      = (const float*)d_in[1];
    const float* basis    = (const float*)d_in[2];
    const float* w1  = (const float*)d_in[3];
    const float* b1  = (const float*)d_in[4];
    const float* g1  = (const float*)d_in[5];
    const float* be1 = (const float*)d_in[6];
    const float* w2  = (const float*)d_in[7];
    const float* b2  = (const float*)d_in[8];
    const float* g2  = (const float*)d_in[9];
    const float* be2 = (const float*)d_in[10];
    const float* w3  = (const float*)d_in[11];
    float* out = (float*)d_out;

    const int smem_bytes = (5 * BUF) * 4;   // 43520
    cudaFuncSetAttribute(conv_main_kernel,
                         cudaFuncAttributeMaxDynamicSharedMemorySize, smem_bytes);

    prep_kernel<<<MLP_BLOCKS + W3T_BLOCKS, 256>>>(inv, w1, b1, g1, be1,
                                                  w2, b2, g2, be2, w3);
    rw_gemm_kernel<<<GEB * FREQ, 256>>>();
    conv_main_kernel<<<NBLK, 128, smem_bytes>>>(features, basis, out);
}